// round 14
// baseline (speedup 1.0000x reference)
#include <cuda_runtime.h>
#include <math.h>

// AlphaModel: relation-gated blend of parent/child categorical distributions.
// HBM-bound streaming: 400 MB over 10M edges.
// R14: R13 (66.0us) + two tail trims:
//  (a) cosine in e-space: inv factors cancel -> cosv = 1.1 + de*rsqrt(pp*ce)
//      with de=dot(p,e), ce=dot(e,e). Decouples cosine chain from the softmax
//      divide (overlaps the Newton sequence instead of waiting on ch).
//  (b) drop the norm==0 guard: reference guarantees row sums > 0 and softmax
//      ch > 0, so n2 > 0 always. Removes FSETP+FSEL + 13cy pred latency.

#define N_RELS 64
#define BLOCK 256

__device__ __forceinline__ void compute_edge(
    const float p0, const float p1, const float p2,
    const float c0, const float c1, const float c2,
    int r,
    const float* __restrict__ sM, const float* __restrict__ sB,
    float zeps, float nsf,   // nsf = -scale_factor
    float& o0, float& o1, float& o2)
{
    const float* Mr = sM + r * 9;
    // scores = M[r] @ child_probs  (bounded -> __expf safe without max-sub)
    float s0 = fmaf(Mr[0], c0, fmaf(Mr[1], c1, Mr[2] * c2));
    float s1 = fmaf(Mr[3], c0, fmaf(Mr[4], c1, Mr[5] * c2));
    float s2 = fmaf(Mr[6], c0, fmaf(Mr[7], c1, Mr[8] * c2));

    float e0 = __expf(s0);
    float e1 = __expf(s1);
    float e2 = __expf(s2);

    // cosine pieces in e-space: independent of inv -> overlaps the div below
    float de = fmaf(p0, e0, fmaf(p1, e1, p2 * e2));
    float ce = fmaf(e0, e0, fmaf(e1, e1, e2 * e2));
    float pp = fmaf(p0, p0, fmaf(p1, p1, p2 * p2));
    float invn = rsqrtf(pp * ce);            // n2 > 0 guaranteed
    float cosv = fmaf(de, invn, 1.1f);

    float inv = 1.0f / (e0 + e1 + e2);       // IEEE div: ILP filler (keep)
    float ch0 = e0 * inv, ch1 = e1 * inv, ch2 = e2 * inv;

    // alpha = p + b*(ch - p)
    const float* Br = sB + r * 3;
    float a0 = fmaf(Br[0], ch0 - p0, p0);
    float a1 = fmaf(Br[1], ch1 - p1, p1);
    float a2 = fmaf(Br[2], ch2 - p2, p2);

    // (negated) entropy of clipped renormalized blend
    float z0 = fmaxf(zeps, p0 + ch0);
    float z1 = fmaxf(zeps, p1 + ch1);
    float z2 = fmaxf(zeps, p2 + ch2);
    float izs = 1.0f / (z0 + z1 + z2);       // IEEE div: ILP filler (keep)
    z0 *= izs; z1 *= izs; z2 *= izs;
    float negent = fmaf(z0, __logf(z0), fmaf(z1, __logf(z1), z2 * __logf(z2)));

    // scale = sf*cosv/ent = (-sf*cosv)/negent ; chain tail -> fast divide
    float scale = __fdividef(nsf * cosv, negent);
    o0 = a0 * scale;
    o1 = a1 * scale;
    o2 = a2 * scale;
}

__global__ void __launch_bounds__(BLOCK)
alpha_model_kernel(const float* __restrict__ prnt,
                   const float* __restrict__ child,
                   const int*   __restrict__ rels,
                   const float* __restrict__ Mg,
                   const float* __restrict__ betag,
                   const float* __restrict__ zeps_p,
                   const float* __restrict__ sf_p,
                   float* __restrict__ out,
                   int E)
{
    __shared__ float sM[N_RELS * 9];
    __shared__ float sB[N_RELS * 3];
    for (int i = threadIdx.x; i < N_RELS * 9; i += BLOCK) sM[i] = Mg[i];
    for (int i = threadIdx.x; i < N_RELS * 3; i += BLOCK) sB[i] = betag[i];
    __syncthreads();

    const float zeps = __ldg(zeps_p);
    const float nsf  = -__ldg(sf_p);

    int quad  = blockIdx.x * BLOCK + threadIdx.x;  // group of 4 edges
    int nquad = (E + 3) >> 2;
    if (quad >= nquad) return;
    int e0 = quad << 2;

    if (e0 + 4 <= E) {
        const float4* p4 = reinterpret_cast<const float4*>(prnt  + (size_t)e0 * 3);
        const float4* c4 = reinterpret_cast<const float4*>(child + (size_t)e0 * 3);
        const int4*   r4 = reinterpret_cast<const int4*>(rels + e0);

        float4 pa = p4[0], pb = p4[1], pc = p4[2];
        float4 ca = c4[0], cb = c4[1], cc = c4[2];
        int4 rv = r4[0];

        float pv[12] = {pa.x, pa.y, pa.z, pa.w, pb.x, pb.y, pb.z, pb.w, pc.x, pc.y, pc.z, pc.w};
        float cv[12] = {ca.x, ca.y, ca.z, ca.w, cb.x, cb.y, cb.z, cb.w, cc.x, cc.y, cc.z, cc.w};
        int   rr[4]  = {rv.x, rv.y, rv.z, rv.w};

        float ov[12];
#pragma unroll
        for (int j = 0; j < 4; j++) {
            compute_edge(pv[3*j], pv[3*j+1], pv[3*j+2],
                         cv[3*j], cv[3*j+1], cv[3*j+2],
                         rr[j], sM, sB, zeps, nsf,
                         ov[3*j], ov[3*j+1], ov[3*j+2]);
        }

        float4* o4 = reinterpret_cast<float4*>(out + (size_t)e0 * 3);
        o4[0] = make_float4(ov[0], ov[1], ov[2],  ov[3]);
        o4[1] = make_float4(ov[4], ov[5], ov[6],  ov[7]);
        o4[2] = make_float4(ov[8], ov[9], ov[10], ov[11]);
    } else {
        // scalar tail
        for (int e = e0; e < E; e++) {
            float o0, o1, o2;
            compute_edge(prnt[3*e], prnt[3*e+1], prnt[3*e+2],
                         child[3*e], child[3*e+1], child[3*e+2],
                         rels[e], sM, sB, zeps, nsf, o0, o1, o2);
            out[3*e]   = o0;
            out[3*e+1] = o1;
            out[3*e+2] = o2;
        }
    }
}

extern "C" void kernel_launch(void* const* d_in, const int* in_sizes, int n_in,
                              void* d_out, int out_size)
{
    // input order: var_sfx, prnt_probs, child_probs, rels, M, beta, z_epsilon, scale_factor
    const float* prnt  = (const float*)d_in[1];
    const float* child = (const float*)d_in[2];
    const int*   rels  = (const int*)d_in[3];
    const float* Mg    = (const float*)d_in[4];
    const float* betag = (const float*)d_in[5];
    const float* zeps  = (const float*)d_in[6];
    const float* sf    = (const float*)d_in[7];
    float* out = (float*)d_out;

    int E = in_sizes[1] / 3;
    int nquad = (E + 3) >> 2;
    int grid = (nquad + BLOCK - 1) / BLOCK;

    alpha_model_kernel<<<grid, BLOCK>>>(prnt, child, rels, Mg, betag, zeps, sf, out, E);
}